// round 9
// baseline (speedup 1.0000x reference)
#include <cuda_runtime.h>
#include <cstdint>

#define Nn 200000
#define Ee 3200000
#define C  16
#define EPSV 1e-5f
#define SB  512
#define SBLK ((Nn + SB - 1) / SB)   // 391

// ---------------- scratch (no allocations allowed) ----------------
__device__ __align__(16) float g_dinv[Nn];     // rsqrt(deg+1)
__device__ __align__(16) float g_h[Nn * C];    // node features after linear
__device__ __align__(16) float g_agg[Nn * C];  // aggregation result (bias included)
__device__ __align__(16) float g_stats[64];    // layer1: [0:16) sum [16:32) sq; layer2: +32
__device__ int  g_deg[Nn];                     // in-degree (edges only)
__device__ int  g_off[Nn];                     // CSR exclusive offsets
__device__ int  g_cur[Nn];                     // fill cursors
__device__ int  g_tmpI[Nn];                    // scan temp (inclusive)
__device__ int  g_bsum[SB];                    // block sums for scan
__device__ __align__(16) int2 g_csr[Ee];       // {src, __float_as_int(nrm)}

// ---------------- f32x2 packed math helpers ----------------
__device__ __forceinline__ unsigned long long pack2(float a, float b) {
    unsigned long long r;
    asm("mov.b64 %0, {%1, %2};" : "=l"(r) : "r"(__float_as_uint(a)), "r"(__float_as_uint(b)));
    return r;
}
__device__ __forceinline__ void unpack2(float& a, float& b, unsigned long long v) {
    unsigned lo, hi;
    asm("mov.b64 {%0, %1}, %2;" : "=r"(lo), "=r"(hi) : "l"(v));
    a = __uint_as_float(lo);
    b = __uint_as_float(hi);
}
__device__ __forceinline__ unsigned long long fma2(unsigned long long a, unsigned long long b,
                                                   unsigned long long c) {
    unsigned long long d;
    asm("fma.rn.f32x2 %0, %1, %2, %3;" : "=l"(d) : "l"(a), "l"(b), "l"(c));
    return d;
}

// ---------------- init: zero degrees + zero both stats buffers ----------------
__global__ void k_init() {
    int i = blockIdx.x * blockDim.x + threadIdx.x;
    if (i < Nn) g_deg[i] = 0;
    if (blockIdx.x == 0 && threadIdx.x < 64) g_stats[threadIdx.x] = 0.0f;
}

// edge_index is INT32 on device (harness converts int64 -> int32)
__global__ void k_deg_count(const int* __restrict__ ei) {
    int e = blockIdx.x * blockDim.x + threadIdx.x;
    if (e < Ee) {
        unsigned d = (unsigned)ei[Ee + e];
        if (d < Nn) atomicAdd(&g_deg[d], 1);
    }
}

// scan stage 1 (+dinv fused): per-block inclusive scan, record block totals
__global__ void k_scan1() {
    __shared__ int sm[SB];
    int t = threadIdx.x;
    int idx = blockIdx.x * SB + t;
    int v = (idx < Nn) ? g_deg[idx] : 0;
    if (idx < Nn) g_dinv[idx] = rsqrtf((float)(v + 1));  // +1 self-loop
    sm[t] = v;
    __syncthreads();
    for (int o = 1; o < SB; o <<= 1) {
        int a = (t >= o) ? sm[t - o] : 0;
        __syncthreads();
        sm[t] += a;
        __syncthreads();
    }
    if (idx < Nn) g_tmpI[idx] = sm[t];
    if (t == SB - 1) g_bsum[blockIdx.x] = sm[t];
}

// scan stage 2+3 merged: per-block prefix of block sums via reduction, then offsets
__global__ void k_scan3() {
    __shared__ int red[SB];
    int t = threadIdx.x;
    red[t] = (t < blockIdx.x && t < SBLK) ? g_bsum[t] : 0;
    __syncthreads();
    for (int o = SB / 2; o > 0; o >>= 1) {
        if (t < o) red[t] += red[t + o];
        __syncthreads();
    }
    int S = red[0];
    int idx = blockIdx.x * SB + t;
    if (idx < Nn) {
        int excl = g_tmpI[idx] - g_deg[idx] + S;
        g_off[idx] = excl;
        g_cur[idx] = excl;
    }
}

// fill writes EVERY claimed slot (invalid src -> {0, nrm=0}), so gather needs no guard
__global__ void k_fill(const int* __restrict__ ei) {
    int e = blockIdx.x * blockDim.x + threadIdx.x;
    if (e >= Ee) return;
    unsigned s = (unsigned)ei[e];
    unsigned d = (unsigned)ei[Ee + e];
    if (d >= Nn) return;
    int   ssrc = 0;
    float nrm  = 0.0f;
    if (s < Nn) { ssrc = (int)s; nrm = g_dinv[s] * g_dinv[d]; }
    int slot = atomicAdd(&g_cur[d], 1);
    g_csr[slot] = make_int2(ssrc, __float_as_int(nrm));
}

// ---------------- layer 1 linear: g_h = x @ W1 ----------------
// warp handles 4 rows; lane l owns k in {l, l+32, ...}; f32x2 accumulators.
// W smem uses XOR chunk swizzle (slot = c ^ ((k>>1)&3)) -> conflict-free LDS.128.
__global__ void k_lin1(const float* __restrict__ x, const float* __restrict__ W1) {
    __shared__ __align__(16) float Ws[256 * 16];
    int tid = threadIdx.x;
#pragma unroll 4
    for (int i = tid; i < 256 * 16; i += 256) {
        int k = i >> 4, o = i & 15;
        int slot = (o >> 2) ^ ((k >> 1) & 3);
        Ws[(k << 4) + (slot << 2) + (o & 3)] = W1[i];
    }
    __syncthreads();

    int warp = tid >> 5, lane = tid & 31;
    int r0 = (blockIdx.x * 8 + warp) * 4;

    unsigned long long acc2[32];
#pragma unroll
    for (int j = 0; j < 32; j++) acc2[j] = 0ULL;

#pragma unroll
    for (int s = 0; s < 8; s++) {
        int k = (s << 5) | lane;
        float x0 = x[(size_t)(r0 + 0) * 256 + k];
        float x1 = x[(size_t)(r0 + 1) * 256 + k];
        float x2 = x[(size_t)(r0 + 2) * 256 + k];
        float x3 = x[(size_t)(r0 + 3) * 256 + k];
        unsigned long long xp0 = pack2(x0, x0);
        unsigned long long xp1 = pack2(x1, x1);
        unsigned long long xp2 = pack2(x2, x2);
        unsigned long long xp3 = pack2(x3, x3);

        const ulonglong2* wrow = (const ulonglong2*)(Ws + (k << 4));
        int sw = (k >> 1) & 3;
        ulonglong2 wq0 = wrow[0 ^ sw];
        ulonglong2 wq1 = wrow[1 ^ sw];
        ulonglong2 wq2 = wrow[2 ^ sw];
        ulonglong2 wq3 = wrow[3 ^ sw];
        unsigned long long w2[8] = {wq0.x, wq0.y, wq1.x, wq1.y, wq2.x, wq2.y, wq3.x, wq3.y};

#pragma unroll
        for (int o2 = 0; o2 < 8; o2++) {
            acc2[0 * 8 + o2] = fma2(xp0, w2[o2], acc2[0 * 8 + o2]);
            acc2[1 * 8 + o2] = fma2(xp1, w2[o2], acc2[1 * 8 + o2]);
            acc2[2 * 8 + o2] = fma2(xp2, w2[o2], acc2[2 * 8 + o2]);
            acc2[3 * 8 + o2] = fma2(xp3, w2[o2], acc2[3 * 8 + o2]);
        }
    }

    float vals[64];
#pragma unroll
    for (int j = 0; j < 32; j++) unpack2(vals[2 * j], vals[2 * j + 1], acc2[j]);

    const unsigned FULL = 0xffffffffu;
#define FOLD_STAGE(n, m)                                                        \
    {                                                                           \
        bool hi = (lane & (m)) != 0;                                            \
        _Pragma("unroll")                                                       \
        for (int t = 0; t < (n) / 2; t++) {                                     \
            float mine = hi ? vals[t + (n) / 2] : vals[t];                      \
            float send = hi ? vals[t] : vals[t + (n) / 2];                      \
            vals[t] = mine + __shfl_xor_sync(FULL, send, (m));                  \
        }                                                                       \
    }
    FOLD_STAGE(64, 16)
    FOLD_STAGE(32, 8)
    FOLD_STAGE(16, 4)
    FOLD_STAGE(8, 2)
    FOLD_STAGE(4, 1)
#undef FOLD_STAGE

    int i = (((lane >> 4) & 1) << 1) | ((lane >> 3) & 1);
    int o = (((lane >> 2) & 1) << 3) | (((lane >> 1) & 1) << 2) | ((lane & 1) << 1);
    int row = r0 + i;
    float2 st;
    st.x = vals[0];
    st.y = vals[1];
    ((float2*)g_h)[row * 8 + (o >> 1)] = st;
}

// ---------------- warp-per-node gather ----------------
// 32 lanes = 8 edge-groups x 4 column-lanes. CSR reads contiguous 64B per warp-iter.
// Divergence bound by this node's own degree (not max over 8 nodes).
__device__ __forceinline__ float4 gather_warp(int node, int eg, int t) {
    int beg = g_off[node];
    int cnt = g_deg[node];
    const float4* h4 = (const float4*)g_h;
    float4 acc = make_float4(0.0f, 0.0f, 0.0f, 0.0f);
#pragma unroll 2
    for (int i = eg; i < cnt; i += 8) {
        int2 r = g_csr[beg + i];
        float w = __int_as_float(r.y);
        float4 v = h4[((unsigned)r.x << 2) + t];
        acc.x = fmaf(w, v.x, acc.x);
        acc.y = fmaf(w, v.y, acc.y);
        acc.z = fmaf(w, v.z, acc.z);
        acc.w = fmaf(w, v.w, acc.w);
    }
    const unsigned FULL = 0xffffffffu;
#pragma unroll
    for (int m = 4; m <= 16; m <<= 1) {
        acc.x += __shfl_xor_sync(FULL, acc.x, m);
        acc.y += __shfl_xor_sync(FULL, acc.y, m);
        acc.z += __shfl_xor_sync(FULL, acc.z, m);
        acc.w += __shfl_xor_sync(FULL, acc.w, m);
    }
    return acc;
}

// gather + bias + fused BN stats; block = 1024 threads = 32 warps = 32 nodes
__global__ void k_gather_agg(const float* __restrict__ bias, int so) {
    __shared__ float sh_s[32 * 16];
    __shared__ float sh_q[32 * 16];
    int tid  = threadIdx.x;
    int warp = tid >> 5;
    int lane = tid & 31;
    int node = blockIdx.x * 32 + warp;
    int t    = lane & 3;
    int eg   = lane >> 2;

    float4 acc = gather_warp(node, eg, t);

    if (lane < 4) {
        float di = g_dinv[node];
        float ss = di * di;
        const float4* h4 = (const float4*)g_h;
        float4 a  = h4[(node << 2) + t];
        float4 b4 = ((const float4*)bias)[t];
        acc.x = fmaf(ss, a.x, acc.x) + b4.x;
        acc.y = fmaf(ss, a.y, acc.y) + b4.y;
        acc.z = fmaf(ss, a.z, acc.z) + b4.z;
        acc.w = fmaf(ss, a.w, acc.w) + b4.w;
        ((float4*)g_agg)[(node << 2) + t] = acc;
        ((float4*)sh_s)[warp * 4 + t] = acc;
        float4 q;
        q.x = acc.x * acc.x; q.y = acc.y * acc.y;
        q.z = acc.z * acc.z; q.w = acc.w * acc.w;
        ((float4*)sh_q)[warp * 4 + t] = q;
    }
    __syncthreads();
    if (tid < 32) {
        int col = tid & 15;
        float v = 0.0f;
        if (tid < 16) {
#pragma unroll 8
            for (int w = 0; w < 32; w++) v += sh_s[w * 16 + col];
        } else {
#pragma unroll 8
            for (int w = 0; w < 32; w++) v += sh_q[w * 16 + col];
        }
        atomicAdd(&g_stats[so + tid], v);
    }
}

// final-layer gather -> harness output (+bias), no stats
__global__ void k_gather_out(float* __restrict__ out, const float* __restrict__ bias) {
    int tid  = threadIdx.x;
    int warp = tid >> 5;
    int lane = tid & 31;
    int node = blockIdx.x * 32 + warp;
    int t    = lane & 3;
    int eg   = lane >> 2;

    float4 acc = gather_warp(node, eg, t);

    if (lane < 4) {
        float di = g_dinv[node];
        float ss = di * di;
        const float4* h4 = (const float4*)g_h;
        float4 a  = h4[(node << 2) + t];
        float4 b4 = ((const float4*)bias)[t];
        acc.x = fmaf(ss, a.x, acc.x) + b4.x;
        acc.y = fmaf(ss, a.y, acc.y) + b4.y;
        acc.z = fmaf(ss, a.z, acc.z) + b4.z;
        acc.w = fmaf(ss, a.w, acc.w) + b4.w;
        ((float4*)out)[(node << 2) + t] = acc;
    }
}

// ---------------- fused BNfinal+BN+ReLU+16x16 linear ----------------
// g_agg already contains (agg + bias); stats at g_stats[so..so+32)
__global__ void k_lin_mid(const float* __restrict__ W,
                          const float* __restrict__ gamma,
                          const float* __restrict__ beta, int so) {
    __shared__ float Ws[256];
    __shared__ float sc_s[16], sh_s[16];
    if (threadIdx.x < 256) Ws[threadIdx.x] = W[threadIdx.x];
    if (threadIdx.x < 16) {
        float sum = g_stats[so + threadIdx.x];
        float sq  = g_stats[so + 16 + threadIdx.x];
        float mu  = sum / (float)Nn;
        float var = sq / (float)Nn - mu * mu;
        float sc  = gamma[threadIdx.x] * rsqrtf(var + EPSV);
        sc_s[threadIdx.x] = sc;
        sh_s[threadIdx.x] = beta[threadIdx.x] - mu * sc;
    }
    __syncthreads();

    int row = blockIdx.x * blockDim.x + threadIdx.x;
    if (row >= Nn) return;

    float z[16];
    const float4* ap = (const float4*)(g_agg + (size_t)row * 16);
#pragma unroll
    for (int j = 0; j < 4; j++) {
        float4 v = ap[j];
        const float* vv = (const float*)&v;
#pragma unroll
        for (int i = 0; i < 4; i++) {
            int k = j * 4 + i;
            z[k] = fmaxf(fmaf(sc_s[k], vv[i], sh_s[k]), 0.0f);
        }
    }

    float o[16];
#pragma unroll
    for (int c = 0; c < 16; c++) o[c] = 0.0f;
#pragma unroll
    for (int k = 0; k < 16; k++) {
        float zk = z[k];
        const float* wr = &Ws[k * 16];
#pragma unroll
        for (int c = 0; c < 16; c++) o[c] = fmaf(zk, wr[c], o[c]);
    }

    float4* hv = (float4*)(g_h + (size_t)row * 16);
#pragma unroll
    for (int j = 0; j < 4; j++) {
        float4 hh;
        hh.x = o[j*4+0]; hh.y = o[j*4+1]; hh.z = o[j*4+2]; hh.w = o[j*4+3];
        hv[j] = hh;
    }
}

// ---------------- launch ----------------
extern "C" void kernel_launch(void* const* d_in, const int* in_sizes, int n_in,
                              void* d_out, int out_size) {
    // Identify inputs by SIZE (robust to metadata ordering)
    const float* x  = nullptr;
    const int*   ei = nullptr;
    const float* W1 = nullptr;
    const float* W2 = nullptr;
    const float* W3 = nullptr;
    const float* v16[8] = {nullptr};
    int n16 = 0;
    for (int i = 0; i < n_in; i++) {
        int sz = in_sizes[i];
        if      (sz == 51200000) x  = (const float*)d_in[i];
        else if (sz == 6400000)  ei = (const int*)d_in[i];
        else if (sz == 4096)     W1 = (const float*)d_in[i];
        else if (sz == 256)      { if (!W2) W2 = (const float*)d_in[i]; else W3 = (const float*)d_in[i]; }
        else if (sz == 16 && n16 < 8) v16[n16++] = (const float*)d_in[i];
    }
    const float* b1  = v16[0];
    const float* g1  = v16[1];
    const float* be1 = v16[2];
    const float* b2  = v16[3];
    const float* g2  = v16[4];
    const float* be2 = v16[5];
    const float* b3  = v16[6];
    float* out = (float*)d_out;

    const int TB    = 256;
    const int nblk  = (Nn + TB - 1) / TB;
    const int eblk  = (Ee + TB - 1) / TB;
    const int l1blk = Nn / 32;              // 6250 (8 warps x 4 rows, exact)
    const int gblk  = Nn / 32;              // 6250 blocks x 32 warps = 200000 nodes exact

    // ----- CSR build (once) -----
    k_init<<<nblk, TB>>>();
    k_deg_count<<<eblk, TB>>>(ei);
    k_scan1<<<SBLK, SB>>>();
    k_scan3<<<SBLK, SB>>>();
    k_fill<<<eblk, TB>>>(ei);

    // ----- layer 1 -----
    k_lin1<<<l1blk, TB>>>(x, W1);
    k_gather_agg<<<gblk, 1024>>>(b1, 0);
    // ----- layer 2 -----
    k_lin_mid<<<nblk, TB>>>(W2, g1, be1, 0);
    k_gather_agg<<<gblk, 1024>>>(b2, 32);
    // ----- layer 3 -----
    k_lin_mid<<<nblk, TB>>>(W3, g2, be2, 32);
    k_gather_out<<<gblk, 1024>>>(out, b3);
}

// round 10
// speedup vs baseline: 1.3331x; 1.3331x over previous
#include <cuda_runtime.h>
#include <cstdint>

#define Nn 200000
#define Ee 3200000
#define C  16
#define EPSV 1e-5f
#define SB  512
#define SBLK ((Nn + SB - 1) / SB)   // 391

// ---------------- scratch (no allocations allowed) ----------------
__device__ __align__(16) float g_dinv[Nn];     // rsqrt(deg+1)
__device__ __align__(16) float g_h[Nn * C];    // node features after linear
__device__ __align__(16) float g_agg[Nn * C];  // aggregation result (bias included)
__device__ __align__(16) float g_stats[64];    // layer1: [0:16) sum [16:32) sq; layer2: +32
__device__ int  g_deg[Nn];                     // in-degree (edges only)
__device__ int  g_off[Nn];                     // CSR exclusive offsets
__device__ int  g_cur[Nn];                     // fill cursors
__device__ int  g_tmpI[Nn];                    // scan temp (inclusive)
__device__ int  g_bsum[SB];                    // block sums for scan
__device__ __align__(16) int2 g_csr[Ee];       // {src, __float_as_int(nrm)}

// ---------------- f32x2 packed math helpers ----------------
__device__ __forceinline__ unsigned long long pack2(float a, float b) {
    unsigned long long r;
    asm("mov.b64 %0, {%1, %2};" : "=l"(r) : "r"(__float_as_uint(a)), "r"(__float_as_uint(b)));
    return r;
}
__device__ __forceinline__ void unpack2(float& a, float& b, unsigned long long v) {
    unsigned lo, hi;
    asm("mov.b64 {%0, %1}, %2;" : "=r"(lo), "=r"(hi) : "l"(v));
    a = __uint_as_float(lo);
    b = __uint_as_float(hi);
}
__device__ __forceinline__ unsigned long long fma2(unsigned long long a, unsigned long long b,
                                                   unsigned long long c) {
    unsigned long long d;
    asm("fma.rn.f32x2 %0, %1, %2, %3;" : "=l"(d) : "l"(a), "l"(b), "l"(c));
    return d;
}

// ---------------- init: zero degrees + zero both stats buffers ----------------
__global__ void k_init() {
    int i = blockIdx.x * blockDim.x + threadIdx.x;
    if (i < Nn) g_deg[i] = 0;
    if (blockIdx.x == 0 && threadIdx.x < 64) g_stats[threadIdx.x] = 0.0f;
}

// edge_index is INT32 on device (harness converts int64 -> int32)
__global__ void k_deg_count(const int* __restrict__ ei) {
    int e = blockIdx.x * blockDim.x + threadIdx.x;
    if (e < Ee) {
        unsigned d = (unsigned)ei[Ee + e];
        if (d < Nn) atomicAdd(&g_deg[d], 1);
    }
}

// scan stage 1 (+dinv fused): per-block inclusive scan, record block totals
__global__ void k_scan1() {
    __shared__ int sm[SB];
    int t = threadIdx.x;
    int idx = blockIdx.x * SB + t;
    int v = (idx < Nn) ? g_deg[idx] : 0;
    if (idx < Nn) g_dinv[idx] = rsqrtf((float)(v + 1));  // +1 self-loop
    sm[t] = v;
    __syncthreads();
    for (int o = 1; o < SB; o <<= 1) {
        int a = (t >= o) ? sm[t - o] : 0;
        __syncthreads();
        sm[t] += a;
        __syncthreads();
    }
    if (idx < Nn) g_tmpI[idx] = sm[t];
    if (t == SB - 1) g_bsum[blockIdx.x] = sm[t];
}

// scan stage 2+3 merged: per-block prefix of block sums via reduction, then offsets
__global__ void k_scan3() {
    __shared__ int red[SB];
    int t = threadIdx.x;
    red[t] = (t < blockIdx.x && t < SBLK) ? g_bsum[t] : 0;
    __syncthreads();
    for (int o = SB / 2; o > 0; o >>= 1) {
        if (t < o) red[t] += red[t + o];
        __syncthreads();
    }
    int S = red[0];
    int idx = blockIdx.x * SB + t;
    if (idx < Nn) {
        int excl = g_tmpI[idx] - g_deg[idx] + S;
        g_off[idx] = excl;
        g_cur[idx] = excl;
    }
}

// fill writes EVERY claimed slot (invalid src -> {0, nrm=0}), so gather needs no guard
__global__ void k_fill(const int* __restrict__ ei) {
    int e = blockIdx.x * blockDim.x + threadIdx.x;
    if (e >= Ee) return;
    unsigned s = (unsigned)ei[e];
    unsigned d = (unsigned)ei[Ee + e];
    if (d >= Nn) return;
    int   ssrc = 0;
    float nrm  = 0.0f;
    if (s < Nn) { ssrc = (int)s; nrm = g_dinv[s] * g_dinv[d]; }
    int slot = atomicAdd(&g_cur[d], 1);
    g_csr[slot] = make_int2(ssrc, __float_as_int(nrm));
}

// ---------------- layer 1 linear: g_h = x @ W1 ----------------
// warp handles 4 rows; lane l owns k in {l, l+32, ...}; f32x2 accumulators.
// W smem uses XOR chunk swizzle (slot = c ^ ((k>>1)&3)) -> conflict-free LDS.128 phases.
__global__ void k_lin1(const float* __restrict__ x, const float* __restrict__ W1) {
    __shared__ __align__(16) float Ws[256 * 16];
    int tid = threadIdx.x;
#pragma unroll 4
    for (int i = tid; i < 256 * 16; i += 256) {
        int k = i >> 4, o = i & 15;
        int slot = (o >> 2) ^ ((k >> 1) & 3);
        Ws[(k << 4) + (slot << 2) + (o & 3)] = W1[i];
    }
    __syncthreads();

    int warp = tid >> 5, lane = tid & 31;
    int r0 = (blockIdx.x * 8 + warp) * 4;

    unsigned long long acc2[32];
#pragma unroll
    for (int j = 0; j < 32; j++) acc2[j] = 0ULL;

#pragma unroll
    for (int s = 0; s < 8; s++) {
        int k = (s << 5) | lane;
        float x0 = x[(size_t)(r0 + 0) * 256 + k];
        float x1 = x[(size_t)(r0 + 1) * 256 + k];
        float x2 = x[(size_t)(r0 + 2) * 256 + k];
        float x3 = x[(size_t)(r0 + 3) * 256 + k];
        unsigned long long xp0 = pack2(x0, x0);
        unsigned long long xp1 = pack2(x1, x1);
        unsigned long long xp2 = pack2(x2, x2);
        unsigned long long xp3 = pack2(x3, x3);

        const ulonglong2* wrow = (const ulonglong2*)(Ws + (k << 4));
        int sw = (k >> 1) & 3;
        ulonglong2 wq0 = wrow[0 ^ sw];
        ulonglong2 wq1 = wrow[1 ^ sw];
        ulonglong2 wq2 = wrow[2 ^ sw];
        ulonglong2 wq3 = wrow[3 ^ sw];
        unsigned long long w2[8] = {wq0.x, wq0.y, wq1.x, wq1.y, wq2.x, wq2.y, wq3.x, wq3.y};

#pragma unroll
        for (int o2 = 0; o2 < 8; o2++) {
            acc2[0 * 8 + o2] = fma2(xp0, w2[o2], acc2[0 * 8 + o2]);
            acc2[1 * 8 + o2] = fma2(xp1, w2[o2], acc2[1 * 8 + o2]);
            acc2[2 * 8 + o2] = fma2(xp2, w2[o2], acc2[2 * 8 + o2]);
            acc2[3 * 8 + o2] = fma2(xp3, w2[o2], acc2[3 * 8 + o2]);
        }
    }

    float vals[64];
#pragma unroll
    for (int j = 0; j < 32; j++) unpack2(vals[2 * j], vals[2 * j + 1], acc2[j]);

    const unsigned FULL = 0xffffffffu;
#define FOLD_STAGE(n, m)                                                        \
    {                                                                           \
        bool hi = (lane & (m)) != 0;                                            \
        _Pragma("unroll")                                                       \
        for (int t = 0; t < (n) / 2; t++) {                                     \
            float mine = hi ? vals[t + (n) / 2] : vals[t];                      \
            float send = hi ? vals[t] : vals[t + (n) / 2];                      \
            vals[t] = mine + __shfl_xor_sync(FULL, send, (m));                  \
        }                                                                       \
    }
    FOLD_STAGE(64, 16)
    FOLD_STAGE(32, 8)
    FOLD_STAGE(16, 4)
    FOLD_STAGE(8, 2)
    FOLD_STAGE(4, 1)
#undef FOLD_STAGE

    int i = (((lane >> 4) & 1) << 1) | ((lane >> 3) & 1);
    int o = (((lane >> 2) & 1) << 3) | (((lane >> 1) & 1) << 2) | ((lane & 1) << 1);
    int row = r0 + i;
    float2 st;
    st.x = vals[0];
    st.y = vals[1];
    ((float2*)g_h)[row * 8 + (o >> 1)] = st;
}

// ---------------- gather core (R8 quad-per-node form): ----------------
// acc = dinv^2*h[node] + sum_e nrm*h[src]; int4 double-record loads for 2x MLP.
__device__ __forceinline__ float4 gather_node(int node, int t) {
    int beg = g_off[node];
    int cnt = g_deg[node];
    int end = beg + cnt;
    float di = g_dinv[node];
    float ss = di * di;

    const float4* h4 = (const float4*)g_h;
    float4 a = h4[(node << 2) + t];
    float4 acc;
    acc.x = ss * a.x; acc.y = ss * a.y; acc.z = ss * a.z; acc.w = ss * a.w;

    int i = beg;
    if ((i & 1) && i < end) {
        int2 r = g_csr[i++];
        float w = __int_as_float(r.y);
        float4 v = h4[(r.x << 2) + t];
        acc.x = fmaf(w, v.x, acc.x);
        acc.y = fmaf(w, v.y, acc.y);
        acc.z = fmaf(w, v.z, acc.z);
        acc.w = fmaf(w, v.w, acc.w);
    }
    for (; i + 1 < end; i += 2) {
        int4 rr = *(const int4*)&g_csr[i];   // 2 records: {s0, n0, s1, n1}
        float w0 = __int_as_float(rr.y);
        float w1 = __int_as_float(rr.w);
        float4 v0 = h4[(rr.x << 2) + t];
        float4 v1 = h4[(rr.z << 2) + t];
        acc.x = fmaf(w0, v0.x, acc.x);
        acc.y = fmaf(w0, v0.y, acc.y);
        acc.z = fmaf(w0, v0.z, acc.z);
        acc.w = fmaf(w0, v0.w, acc.w);
        acc.x = fmaf(w1, v1.x, acc.x);
        acc.y = fmaf(w1, v1.y, acc.y);
        acc.z = fmaf(w1, v1.z, acc.z);
        acc.w = fmaf(w1, v1.w, acc.w);
    }
    if (i < end) {
        int2 r = g_csr[i];
        float w = __int_as_float(r.y);
        float4 v = h4[(r.x << 2) + t];
        acc.x = fmaf(w, v.x, acc.x);
        acc.y = fmaf(w, v.y, acc.y);
        acc.z = fmaf(w, v.z, acc.z);
        acc.w = fmaf(w, v.w, acc.w);
    }
    return acc;
}

// gather + bias + fused BN stats (sum/sumsq per column into g_stats[so..])
// grid exact: 800000 threads = 3125 blocks x 256
__global__ void k_gather_agg(const float* __restrict__ bias, int so) {
    __shared__ float bsum[16], bsq[16];
    if (threadIdx.x < 16) { bsum[threadIdx.x] = 0.0f; bsq[threadIdx.x] = 0.0f; }
    __syncthreads();

    int gid  = blockIdx.x * blockDim.x + threadIdx.x;
    int node = gid >> 2;
    int t    = gid & 3;
    int lane = threadIdx.x & 31;

    float4 acc = gather_node(node, t);
    float4 b4  = ((const float4*)bias)[t];
    acc.x += b4.x; acc.y += b4.y; acc.z += b4.z; acc.w += b4.w;
    ((float4*)g_agg)[(node << 2) + t] = acc;

    float4 s1 = acc;
    float4 s2;
    s2.x = acc.x * acc.x; s2.y = acc.y * acc.y; s2.z = acc.z * acc.z; s2.w = acc.w * acc.w;
    const unsigned FULL = 0xffffffffu;
#pragma unroll
    for (int m = 4; m <= 16; m <<= 1) {
        s1.x += __shfl_xor_sync(FULL, s1.x, m);
        s1.y += __shfl_xor_sync(FULL, s1.y, m);
        s1.z += __shfl_xor_sync(FULL, s1.z, m);
        s1.w += __shfl_xor_sync(FULL, s1.w, m);
        s2.x += __shfl_xor_sync(FULL, s2.x, m);
        s2.y += __shfl_xor_sync(FULL, s2.y, m);
        s2.z += __shfl_xor_sync(FULL, s2.z, m);
        s2.w += __shfl_xor_sync(FULL, s2.w, m);
    }
    if (lane < 4) {
        atomicAdd(&bsum[t * 4 + 0], s1.x);
        atomicAdd(&bsum[t * 4 + 1], s1.y);
        atomicAdd(&bsum[t * 4 + 2], s1.z);
        atomicAdd(&bsum[t * 4 + 3], s1.w);
        atomicAdd(&bsq[t * 4 + 0], s2.x);
        atomicAdd(&bsq[t * 4 + 1], s2.y);
        atomicAdd(&bsq[t * 4 + 2], s2.z);
        atomicAdd(&bsq[t * 4 + 3], s2.w);
    }
    __syncthreads();
    if (threadIdx.x < 16) {
        atomicAdd(&g_stats[so + threadIdx.x], bsum[threadIdx.x]);
        atomicAdd(&g_stats[so + 16 + threadIdx.x], bsq[threadIdx.x]);
    }
}

__global__ void k_gather_out(float* __restrict__ out, const float* __restrict__ bias) {
    int gid  = blockIdx.x * blockDim.x + threadIdx.x;
    int node = gid >> 2;
    if (node >= Nn) return;
    int t = gid & 3;
    float4 acc = gather_node(node, t);
    float4 b4  = ((const float4*)bias)[t];
    acc.x += b4.x; acc.y += b4.y; acc.z += b4.z; acc.w += b4.w;
    ((float4*)out)[(node << 2) + t] = acc;
}

// ---------------- fused BNfinal+BN+ReLU+16x16 linear ----------------
__global__ void k_lin_mid(const float* __restrict__ W,
                          const float* __restrict__ gamma,
                          const float* __restrict__ beta, int so) {
    __shared__ float Ws[256];
    __shared__ float sc_s[16], sh_s[16];
    if (threadIdx.x < 256) Ws[threadIdx.x] = W[threadIdx.x];
    if (threadIdx.x < 16) {
        float sum = g_stats[so + threadIdx.x];
        float sq  = g_stats[so + 16 + threadIdx.x];
        float mu  = sum / (float)Nn;
        float var = sq / (float)Nn - mu * mu;
        float sc  = gamma[threadIdx.x] * rsqrtf(var + EPSV);
        sc_s[threadIdx.x] = sc;
        sh_s[threadIdx.x] = beta[threadIdx.x] - mu * sc;
    }
    __syncthreads();

    int row = blockIdx.x * blockDim.x + threadIdx.x;
    if (row >= Nn) return;

    float z[16];
    const float4* ap = (const float4*)(g_agg + (size_t)row * 16);
#pragma unroll
    for (int j = 0; j < 4; j++) {
        float4 v = ap[j];
        const float* vv = (const float*)&v;
#pragma unroll
        for (int i = 0; i < 4; i++) {
            int k = j * 4 + i;
            z[k] = fmaxf(fmaf(sc_s[k], vv[i], sh_s[k]), 0.0f);
        }
    }

    float o[16];
#pragma unroll
    for (int c = 0; c < 16; c++) o[c] = 0.0f;
#pragma unroll
    for (int k = 0; k < 16; k++) {
        float zk = z[k];
        const float* wr = &Ws[k * 16];
#pragma unroll
        for (int c = 0; c < 16; c++) o[c] = fmaf(zk, wr[c], o[c]);
    }

    float4* hv = (float4*)(g_h + (size_t)row * 16);
#pragma unroll
    for (int j = 0; j < 4; j++) {
        float4 hh;
        hh.x = o[j*4+0]; hh.y = o[j*4+1]; hh.z = o[j*4+2]; hh.w = o[j*4+3];
        hv[j] = hh;
    }
}

// ---------------- launch ----------------
extern "C" void kernel_launch(void* const* d_in, const int* in_sizes, int n_in,
                              void* d_out, int out_size) {
    // Identify inputs by SIZE (robust to metadata ordering)
    const float* x  = nullptr;
    const int*   ei = nullptr;
    const float* W1 = nullptr;
    const float* W2 = nullptr;
    const float* W3 = nullptr;
    const float* v16[8] = {nullptr};
    int n16 = 0;
    for (int i = 0; i < n_in; i++) {
        int sz = in_sizes[i];
        if      (sz == 51200000) x  = (const float*)d_in[i];
        else if (sz == 6400000)  ei = (const int*)d_in[i];
        else if (sz == 4096)     W1 = (const float*)d_in[i];
        else if (sz == 256)      { if (!W2) W2 = (const float*)d_in[i]; else W3 = (const float*)d_in[i]; }
        else if (sz == 16 && n16 < 8) v16[n16++] = (const float*)d_in[i];
    }
    const float* b1  = v16[0];
    const float* g1  = v16[1];
    const float* be1 = v16[2];
    const float* b2  = v16[3];
    const float* g2  = v16[4];
    const float* be2 = v16[5];
    const float* b3  = v16[6];
    float* out = (float*)d_out;

    const int TB    = 256;
    const int nblk  = (Nn + TB - 1) / TB;
    const int eblk  = (Ee + TB - 1) / TB;
    const int l1blk = Nn / 32;              // 6250 (8 warps x 4 rows, exact)
    const int gblk  = (Nn * 4) / TB;        // 3125 exact

    // ----- CSR build + lin1 (lin1 at launch index 3 => it lands in the ncu slot) -----
    k_init<<<nblk, TB>>>();                 // 0
    k_deg_count<<<eblk, TB>>>(ei);          // 1
    k_scan1<<<SBLK, SB>>>();                // 2
    k_lin1<<<l1blk, TB>>>(x, W1);           // 3  <-- profiled
    k_scan3<<<SBLK, SB>>>();                // 4
    k_fill<<<eblk, TB>>>(ei);               // 5

    // ----- layer 1 -----
    k_gather_agg<<<gblk, TB>>>(b1, 0);      // 6
    // ----- layer 2 -----
    k_lin_mid<<<nblk, TB>>>(W2, g1, be1, 0);    // 7
    k_gather_agg<<<gblk, TB>>>(b2, 32);         // 8
    // ----- layer 3 -----
    k_lin_mid<<<nblk, TB>>>(W3, g2, be2, 32);   // 9
    k_gather_out<<<gblk, TB>>>(out, b3);        // 10
}